// round 1
// baseline (speedup 1.0000x reference)
#include <cuda_runtime.h>

// Depth-to-space r=4, x-major channel ordering:
//   out[b, c, y, x] = in[b, c*16 + 4*(x%4) + (y%4), y/4, x/4]
// in : (16, 4096, 32, 32) fp32
// out: (16, 256, 128, 128) fp32
//
// Each thread handles one (b, c, y, xq) where xq indexes a group of 4 xb
// values (8 groups per row of 32). It loads one float4 from each of the 4
// source channels (xr = 0..3), transposes 4x4 in registers, and writes 4
// contiguous float4 to the output row. Both loads and stores are fully
// coalesced 16B vector accesses.

__global__ void __launch_bounds__(256) scale_transfer_kernel(
    const float4* __restrict__ in4, float4* __restrict__ out4)
{
    int tid = blockIdx.x * blockDim.x + threadIdx.x;
    // tid layout: b[4] c[8] y[7] xq[3]  -> 16*256*128*8 = 4,194,304 threads
    int xq = tid & 7;          // which float4 along the 32-wide input row
    int y  = (tid >> 3) & 127;
    int c  = (tid >> 10) & 255;
    int b  = tid >> 18;

    int yr = y & 3;
    int yb = y >> 2;

    // input in float4 units: channel row = 8 float4, channel = 32*8 = 256 float4
    // cin = c*16 + 4*xr + yr  -> base at xr=0, stride 4 channels = 1024 float4
    int ibase = ((b * 4096 + c * 16 + yr) * 32 + yb) * 8 + xq;

    float4 r0 = in4[ibase];
    float4 r1 = in4[ibase + 1024];
    float4 r2 = in4[ibase + 2048];
    float4 r3 = in4[ibase + 3072];

    // output in float4 units: row = 32 float4; this thread owns 4 consecutive
    int obase = ((b * 256 + c) * 128 + y) * 32 + (xq << 2);

    out4[obase + 0] = make_float4(r0.x, r1.x, r2.x, r3.x);
    out4[obase + 1] = make_float4(r0.y, r1.y, r2.y, r3.y);
    out4[obase + 2] = make_float4(r0.z, r1.z, r2.z, r3.z);
    out4[obase + 3] = make_float4(r0.w, r1.w, r2.w, r3.w);
}

extern "C" void kernel_launch(void* const* d_in, const int* in_sizes, int n_in,
                              void* d_out, int out_size)
{
    const float4* in4 = (const float4*)d_in[0];
    float4* out4 = (float4*)d_out;

    const int total_threads = 16 * 256 * 128 * 8;  // 4,194,304
    const int block = 256;
    const int grid = total_threads / block;        // 16384

    scale_transfer_kernel<<<grid, block>>>(in4, out4);
}

// round 2
// speedup vs baseline: 1.0367x; 1.0367x over previous
#include <cuda_runtime.h>
#include <cstdint>

// Depth-to-space r=4, x-major channel ordering:
//   out[b, c, y, x] = in[b, c*16 + 4*(x%4) + (y%4), y/4, x/4]
// in : (16, 4096, 32, 32) fp32  -> 256 MB
// out: (16, 256, 128, 128) fp32 -> 256 MB
//
// 256-bit (v8.f32) vector loads/stores: each thread handles one
// (b, c, y, xq8) where xq8 selects an 8-float group of the 32-float input
// row. It loads 8 consecutive floats from each of the 4 source channels
// (xr=0..3), interleaves in registers, and writes 4 x 32B = 128B of
// consecutive output. Every memory access is a full 32B sector.

__global__ void __launch_bounds__(256) scale_transfer_v8_kernel(
    const float* __restrict__ in, float* __restrict__ out)
{
    unsigned tid = blockIdx.x * blockDim.x + threadIdx.x;
    // tid layout: b[4] c[8] y[7] xq8[2]  -> 16*256*128*4 = 2,097,152 threads
    unsigned xq = tid & 3;            // 8-float group within 32-float input row
    unsigned y  = (tid >> 2) & 127;
    unsigned c  = (tid >> 9) & 255;
    unsigned b  = tid >> 17;

    unsigned yr = y & 3;
    unsigned yb = y >> 2;

    // input float index; channel stride for xr is 4 channels = 4*1024 floats
    const float* p =
        in + (((b * 4096u + c * 16u + yr) * 32u + yb) * 32u + xq * 8u);

    float r[4][8];
#pragma unroll
    for (int xr = 0; xr < 4; xr++) {
        const float* q = p + xr * 4096;
        asm volatile(
            "ld.global.nc.v8.f32 {%0,%1,%2,%3,%4,%5,%6,%7}, [%8];"
            : "=f"(r[xr][0]), "=f"(r[xr][1]), "=f"(r[xr][2]), "=f"(r[xr][3]),
              "=f"(r[xr][4]), "=f"(r[xr][5]), "=f"(r[xr][6]), "=f"(r[xr][7])
            : "l"(q));
    }

    // output: 32 consecutive floats (x = xq*32 .. xq*32+31) of row (b,c,y)
    float* o = out + (((b * 256u + c) * 128u + y) * 128u + xq * 32u);

#pragma unroll
    for (int j = 0; j < 4; j++) {
        // out local x = 4*i + xr, group j covers i = 2j, 2j+1
        int i0 = 2 * j, i1 = 2 * j + 1;
        asm volatile(
            "st.global.v8.f32 [%0], {%1,%2,%3,%4,%5,%6,%7,%8};"
            :
            : "l"(o + j * 8),
              "f"(r[0][i0]), "f"(r[1][i0]), "f"(r[2][i0]), "f"(r[3][i0]),
              "f"(r[0][i1]), "f"(r[1][i1]), "f"(r[2][i1]), "f"(r[3][i1])
            : "memory");
    }
}

extern "C" void kernel_launch(void* const* d_in, const int* in_sizes, int n_in,
                              void* d_out, int out_size)
{
    const float* in = (const float*)d_in[0];
    float* out = (float*)d_out;

    const int total_threads = 16 * 256 * 128 * 4;  // 2,097,152
    const int block = 256;
    const int grid = total_threads / block;        // 8192

    scale_transfer_v8_kernel<<<grid, block>>>(in, out);
}